// round 4
// baseline (speedup 1.0000x reference)
#include <cuda_runtime.h>

// Arithmetic nearest-codebook quantizer for the FP4-style codebook
//   [-6,-4,-3,-2,-1.5,-1,-0.75, 0, 0.5,0.75,1,1.5,2,3,4,6]
// Positive magnitudes are spaced 0x00400000 apart in fp32 bit space; every
// decision boundary is an exact bit midpoint. Tie semantics match jnp.argmin
// (first index wins): positives round half-DOWN, negatives half-UP in
// magnitude. Sign-dependent low clamp (0.5 pos / 0.75 neg) and zero
// threshold (a <= 0.25 pos ; a < 0.375 neg).
__device__ __forceinline__ float quant1(float x, float scale, float inv) {
    unsigned int u  = __float_as_uint(x);
    unsigned int nb = u >> 31;
    float as = fabsf(x) * scale;                            // abs is free on FMUL
    unsigned int a  = __float_as_uint(as);
    unsigned int T  = 0x3E800001u + nb * 0x003FFFFFu;       // zero threshold
    unsigned int LO = 0x3F000000u + nb * 0x00400000u;       // low clamp (0.5/0.75)
    unsigned int t  = min(max(a, LO), 0x40C00000u);         // clamp to [lo, 6.0]
    unsigned int q  = (t + 0x001FFFFFu + nb) & 0xFFC00000u; // half-down/half-up
    q |= (u & 0x80000000u);                                 // copysign
    q  = (a < T) ? 0u : q;                                  // dead zone -> 0
    return __uint_as_float(q) * inv;
}

__device__ __forceinline__ float4 quant4(float4 v, float scale, float inv) {
    float4 r;
    r.x = quant1(v.x, scale, inv);
    r.y = quant1(v.y, scale, inv);
    r.z = quant1(v.z, scale, inv);
    r.w = quant1(v.w, scale, inv);
    return r;
}

// Exact-tiling kernel: each block owns exactly 1024 float4 (16 KB).
// Loads: 4x LDG.128 streaming per thread (front-batched for MLP).
// Stores: STS.128 into a 16 KB smem staging tile, then ONE TMA bulk copy
// (cp.async.bulk smem->gmem) per block — removes all STG.128 issue cost
// (12 cyc/instr on the LSU) and the store-side L1tex wavefront traffic.
__global__ void __launch_bounds__(256)
quant_kernel_exact(const float4* __restrict__ x,
                   float4* __restrict__ out,
                   const float* __restrict__ scale_p) {
    __shared__ alignas(16) float4 sbuf[1024];

    float scale = __ldg(scale_p);
    float inv   = 1.0f / scale;

    int tid  = (int)threadIdx.x;
    int base = blockIdx.x * 1024 + tid;

    float4 v0 = __ldcs(x + base);
    float4 v1 = __ldcs(x + base + 256);
    float4 v2 = __ldcs(x + base + 512);
    float4 v3 = __ldcs(x + base + 768);

    sbuf[tid]       = quant4(v0, scale, inv);
    sbuf[tid + 256] = quant4(v1, scale, inv);
    sbuf[tid + 512] = quant4(v2, scale, inv);
    sbuf[tid + 768] = quant4(v3, scale, inv);

    // Order generic-proxy smem writes before the async-proxy bulk copy.
    asm volatile("fence.proxy.async.shared::cta;" ::: "memory");
    __syncthreads();

    if (tid == 0) {
        unsigned int saddr = (unsigned int)__cvta_generic_to_shared(sbuf);
        float4* gdst = out + (size_t)blockIdx.x * 1024;
        asm volatile(
            "cp.async.bulk.global.shared::cta.bulk_group [%0], [%1], %2;"
            :: "l"(gdst), "r"(saddr), "n"(16384) : "memory");
        asm volatile("cp.async.bulk.commit_group;" ::: "memory");
        // Wait until the bulk op has finished READING smem: after that the
        // CTA may exit (smem can be deallocated) while writes drain.
        asm volatile("cp.async.bulk.wait_group.read 0;" ::: "memory");
    }
    __syncthreads();
}

// General fallback (predicated), used only when n doesn't tile exactly.
__global__ void __launch_bounds__(256)
quant_kernel_tail(const float* __restrict__ x,
                  float* __restrict__ out,
                  const float* __restrict__ scale_p,
                  int start, int n) {
    float scale = __ldg(scale_p);
    float inv   = 1.0f / scale;
    int i = start + blockIdx.x * 256 + (int)threadIdx.x;
    if (i < n) out[i] = quant1(x[i], scale, inv);
}

extern "C" void kernel_launch(void* const* d_in, const int* in_sizes, int n_in,
                              void* d_out, int out_size) {
    const float* x     = (const float*)d_in[0];   // [n] fp32
    // d_in[1] (codebook) is folded into the bit arithmetic above.
    const float* scale = (const float*)d_in[2];
    float* out = (float*)d_out;

    int n = in_sizes[0];
    const int ELEMS_PER_BLOCK = 4096;             // 1024 float4 = 16 KB

    int full_blocks = n / ELEMS_PER_BLOCK;
    int covered = full_blocks * ELEMS_PER_BLOCK;

    if (full_blocks > 0) {
        quant_kernel_exact<<<full_blocks, 256>>>(
            (const float4*)x, (float4*)out, scale);
    }
    if (covered < n) {
        int rem = n - covered;
        int blocks = (rem + 255) / 256;
        quant_kernel_tail<<<blocks, 256>>>(x, out, scale, covered, n);
    }
}

// round 5
// speedup vs baseline: 1.1783x; 1.1783x over previous
#include <cuda_runtime.h>

// Arithmetic nearest-codebook quantizer for the FP4-style codebook
//   [-6,-4,-3,-2,-1.5,-1,-0.75, 0, 0.5,0.75,1,1.5,2,3,4,6]
// Positive magnitudes are spaced 0x00400000 apart in fp32 bit space; every
// decision boundary is an exact bit midpoint. Tie semantics match jnp.argmin
// (first index wins): positives round half-DOWN, negatives half-UP in
// magnitude. Sign-dependent low clamp (0.5 pos / 0.75 neg) and zero
// threshold (a <= 0.25 pos ; a < 0.375 neg).
__device__ __forceinline__ float quant1(float x, float scale, float inv) {
    unsigned int u  = __float_as_uint(x);
    unsigned int nb = u >> 31;                              // alu
    float as = fabsf(x) * scale;                            // fma (abs free)
    unsigned int a  = __float_as_uint(as);
    unsigned int T  = 0x3E800001u + nb * 0x003FFFFFu;       // fma (IMAD)
    unsigned int LO = 0x3F000000u + nb * 0x00400000u;       // fma (IMAD)
    unsigned int t  = min(max(a, LO), 0x40C00000u);         // alu x2
    unsigned int q  = (t + 0x001FFFFFu + nb) & 0xFFC00000u; // alu x2
    q |= (u & 0x80000000u);                                 // alu (LOP3)
    q  = (a < T) ? 0u : q;                                  // alu x2
    return __uint_as_float(q) * inv;                        // fma
}

__device__ __forceinline__ float4 quant4(float4 v, float scale, float inv) {
    float4 r;
    r.x = quant1(v.x, scale, inv);
    r.y = quant1(v.y, scale, inv);
    r.z = quant1(v.z, scale, inv);
    r.w = quant1(v.w, scale, inv);
    return r;
}

// Single-wave persistent kernel: grid is sized to exactly fill the chip once
// (no wave transitions, one launch ramp). Each CTA grid-strides over tiles of
// 1024 float4; per iteration 4 front-batched LDG.128 (default caching — the
// 64MB input fits L2 and stays resident across graph replays) and 4 STG.128
// evict-first stores (touch-once data).
__global__ void __launch_bounds__(256)
quant_kernel_persist(const float4* __restrict__ x,
                     float4* __restrict__ out,
                     const float* __restrict__ scale_p,
                     int ntiles) {   // tiles of 1024 float4
    float scale = __ldg(scale_p);
    float inv   = 1.0f / scale;

    int tid = (int)threadIdx.x;

    for (int tile = blockIdx.x; tile < ntiles; tile += gridDim.x) {
        int base = tile * 1024 + tid;

        float4 v0 = x[base];
        float4 v1 = x[base + 256];
        float4 v2 = x[base + 512];
        float4 v3 = x[base + 768];

        __stcs(out + base,       quant4(v0, scale, inv));
        __stcs(out + base + 256, quant4(v1, scale, inv));
        __stcs(out + base + 512, quant4(v2, scale, inv));
        __stcs(out + base + 768, quant4(v3, scale, inv));
    }
}

// General fallback (predicated), for any n not tiling into 4096 elements.
__global__ void __launch_bounds__(256)
quant_kernel_tail(const float* __restrict__ x,
                  float* __restrict__ out,
                  const float* __restrict__ scale_p,
                  int start, int n) {
    float scale = __ldg(scale_p);
    float inv   = 1.0f / scale;
    int i = start + blockIdx.x * 256 + (int)threadIdx.x;
    if (i < n) out[i] = quant1(x[i], scale, inv);
}

extern "C" void kernel_launch(void* const* d_in, const int* in_sizes, int n_in,
                              void* d_out, int out_size) {
    const float* x     = (const float*)d_in[0];   // [n] fp32
    // d_in[1] (codebook) is folded into the bit arithmetic above.
    const float* scale = (const float*)d_in[2];
    float* out = (float*)d_out;

    int n = in_sizes[0];
    const int ELEMS_PER_TILE = 4096;              // 1024 float4

    int ntiles  = n / ELEMS_PER_TILE;
    int covered = ntiles * ELEMS_PER_TILE;

    if (ntiles > 0) {
        // One wave: 148 SMs x 8 CTAs (256 thr, 32 regs -> 8 resident CTAs/SM).
        int grid = 148 * 8;
        if (grid > ntiles) grid = ntiles;
        quant_kernel_persist<<<grid, 256>>>(
            (const float4*)x, (float4*)out, scale, ntiles);
    }
    if (covered < n) {
        int rem = n - covered;
        int blocks = (rem + 255) / 256;
        quant_kernel_tail<<<blocks, 256>>>(x, out, scale, covered, n);
    }
}